// round 9
// baseline (speedup 1.0000x reference)
#include <cuda_runtime.h>
#include <cuda_fp16.h>
#include <math.h>

#define N_USERS 100000
#define N_NODES 150000
#define NNZ     4800000
#define EMB     64
#define N_LAYERS 3
#define BATCH   4096
#define REG_C   1e-5f
#define NE      (N_NODES * EMB)
#define HIST_SZ 150016
#define HIST_BLOCKS 586
#define HIST_GRID (NNZ / 256)            // 18750
#define EGO_GRID ((NE / 4) / 256)        // 9375
#define ROWS_PB 64
#define ECAP    2560                     // staged edges/block (mean 2048, +11 sigma)
#define LGRID   ((N_NODES + ROWS_PB - 1) / ROWS_PB)   // 2344

typedef unsigned long long u64;

// ---------------- scratch (alloc-free rule: __device__ globals) ------------
__device__ float  g_X[(N_LAYERS + 1) * NE];  // 153.6 MB fp32 planes
__device__ __half g_Xh[N_LAYERS * NE];       // 57.6 MB fp16 gather planes
__device__ int    g_hist[HIST_SZ];           // zeroed by scan1 each pass
__device__ int    g_row_start[HIST_SZ];
__device__ int    g_cursor[HIST_SZ];
__device__ int    g_blocksum[HIST_BLOCKS];
__device__ uint2  g_edges[NNZ];              // (col, val) sorted by row

// ---------------- f32x2 packed-math helpers --------------------------------
__device__ __forceinline__ u64 pack2(float lo, float hi) {
    u64 r; asm("mov.b64 %0,{%1,%2};" : "=l"(r) : "f"(lo), "f"(hi)); return r;
}
__device__ __forceinline__ void unpack2(u64 v, float& lo, float& hi) {
    asm("mov.b64 {%0,%1},%2;" : "=f"(lo), "=f"(hi) : "l"(v));
}
__device__ __forceinline__ u64 fma2(u64 a, u64 b, u64 c) {
    u64 d; asm("fma.rn.f32x2 %0,%1,%2,%3;" : "=l"(d) : "l"(a), "l"(b), "l"(c));
    return d;
}

// ---------------- fused: out=0 + edge histogram + ego copy (fp32+fp16) ------
__global__ void hist_ego_kernel(const int* __restrict__ rows,
                                const float* __restrict__ ue,
                                const float* __restrict__ ie,
                                float* out) {
    int b = blockIdx.x;
    if (b == 0 && threadIdx.x == 0) *out = 0.f;
    if (b < HIST_GRID) {
        int e = b * 256 + threadIdx.x;
        atomicAdd(&g_hist[rows[e]], 1);          // no return use -> REDG
    } else {
        int idx = (b - HIST_GRID) * 256 + threadIdx.x;   // float4 index
        const int UF = (N_USERS * EMB) / 4;
        float4 v = (idx < UF) ? ((const float4*)ue)[idx]
                              : ((const float4*)ie)[idx - UF];
        ((float4*)g_X)[idx] = v;
        __half2 h0 = __floats2half2_rn(v.x, v.y);
        __half2 h1 = __floats2half2_rn(v.z, v.w);
        ((uint2*)g_Xh)[idx] = make_uint2(*(unsigned*)&h0, *(unsigned*)&h1);
    }
}

// ---------------- scan stage 1 (self-zeroing hist) ---------------------------
__global__ void scan1_kernel() {
    __shared__ int s[256];
    int t = threadIdx.x;
    int i = blockIdx.x * 256 + t;
    int v = g_hist[i];
    g_hist[i] = 0;
    s[t] = v; __syncthreads();
#pragma unroll
    for (int off = 1; off < 256; off <<= 1) {
        int add = (t >= off) ? s[t - off] : 0;
        __syncthreads();
        s[t] += add;
        __syncthreads();
    }
    g_row_start[i] = s[t] - v;
    if (t == 255) g_blocksum[blockIdx.x] = s[255];
}

// ---------------- scan stage 2+3 fused ---------------------------------------
__global__ void scan23_kernel() {
    __shared__ int red[256];
    int b = blockIdx.x, t = threadIdx.x;
    int acc = 0;
    for (int k = t; k < b; k += 256) acc += g_blocksum[k];
    red[t] = acc; __syncthreads();
#pragma unroll
    for (int off = 128; off; off >>= 1) {
        if (t < off) red[t] += red[t + off];
        __syncthreads();
    }
    int prefix = red[0];
    int i = b * 256 + t;
    int v = g_row_start[i] + prefix;
    g_row_start[i] = v;
    g_cursor[i]    = v;
}

// ---------------- scatter edges into CSR order (ILP1: at ATOMG floor) --------
__global__ void scatter_kernel(const int* __restrict__ rows,
                               const int* __restrict__ cols,
                               const float* __restrict__ vals) {
    int e = blockIdx.x * 256 + threadIdx.x;
    int r = rows[e];
    int pos = atomicAdd(&g_cursor[r], 1);
    g_edges[pos] = make_uint2((unsigned)cols[e], __float_as_uint(vals[e]));
}

// ---------------- FUSED SpMM + dual-GEMM + leaky + normalize ----------------
// Block = 64 consecutive CSR rows, 256 threads.
// Phase 1: stage the block's contiguous edge segment into smem.
// Phase 2: warp w computes rows w*8..w*8+7 (fp16 gathers, fp32 accum) and
//          writes li/in straight into the swizzled smem tile (col c at c^sw).
// Phase 3: GEMMx2 from smem (packed f32x2 FMA) + bias + leaky + row-normalize.
__global__ void __launch_bounds__(256) fused_layer_kernel(
        const float* __restrict__ W1, const float* __restrict__ b1,
        const float* __restrict__ W2, const float* __restrict__ b2,
        int layer) {
    extern __shared__ float sm[];
    float*  W1s   = sm;                         // 4096 floats
    float*  W2s   = sm + 4096;                  // 4096 floats
    float2* li_in = (float2*)(sm + 8192);       // 64x64 float2 (32KB)
    uint2*  se    = (uint2*)(sm + 8192 + 8192); // ECAP uint2 (20KB)
    int*    rs    = (int*)(se + ECAP);          // 65 ints

    const float* __restrict__ xk = g_X + (size_t)layer * NE;
    float* __restrict__ xo       = g_X + (size_t)(layer + 1) * NE;
    const __half2* __restrict__ xh =
        (const __half2*)g_Xh + (size_t)layer * (NE / 2);

    int tid  = threadIdx.x;
    int base = blockIdx.x * ROWS_PB;

#pragma unroll
    for (int it = 0; it < 4; it++) {
        int idx = it * 256 + tid;
        ((float4*)W1s)[idx] = ((const float4*)W1)[idx];
        ((float4*)W2s)[idx] = ((const float4*)W2)[idx];
    }
    if (tid < 65) {
        int ridx = base + tid;                  // clamp: entries >= N_NODES
        if (ridx > N_NODES) ridx = N_NODES;     // all hold NNZ (OOB fix, R8)
        rs[tid] = g_row_start[ridx];
    }
    __syncthreads();

    int s0 = rs[0];
    int n  = rs[64] - s0;
    bool staged = (n <= ECAP);
    if (staged)
        for (int q = tid; q < n; q += 256) se[q] = g_edges[s0 + q];
    __syncthreads();

    // ---- Phase 2: per-warp spmm for 8 rows, li/in into smem tile ----
    int warp = tid >> 5, lane = tid & 31;
#pragma unroll
    for (int rr = 0; rr < 8; rr++) {
        int rl = warp * 8 + rr;                  // local row 0..63
        int s = rs[rl]     - s0;
        int e = rs[rl + 1] - s0;
        float ax = 0.f, ay = 0.f;
        if (staged) {
            int t = s;
            for (; t + 8 <= e; t += 8) {
                float2 xs[8]; float vs[8];
#pragma unroll
                for (int q = 0; q < 8; q++) {
                    uint2 kv = se[t + q];
                    vs[q] = __uint_as_float(kv.y);
                    xs[q] = __half22float2(xh[(size_t)kv.x * 32 + lane]);
                }
#pragma unroll
                for (int q = 0; q < 8; q++) {
                    ax += vs[q] * xs[q].x;
                    ay += vs[q] * xs[q].y;
                }
            }
            for (; t < e; t++) {
                uint2 kv = se[t];
                float2 xv = __half22float2(xh[(size_t)kv.x * 32 + lane]);
                float v = __uint_as_float(kv.y);
                ax += v * xv.x;
                ay += v * xv.y;
            }
        } else {                                  // safety fallback (unused)
            const uint2* ep = g_edges + s0;
            for (int t = s; t < e; t++) {
                uint2 kv = ep[t];
                float2 xv = __half22float2(xh[(size_t)kv.x * 32 + lane]);
                float v = __uint_as_float(kv.y);
                ax += v * xv.x;
                ay += v * xv.y;
            }
        }
        // li/in for cols 2*lane, 2*lane+1 of row rl; clamp guard-row read
        int rrow = base + rl;
        if (rrow >= N_NODES) rrow = N_NODES - 1;  // value discarded at write
        float2 a2 = *(const float2*)(xk + (size_t)rrow * EMB + lane * 2);
        float lix = ax + a2.x, liy = ay + a2.y;
        float inx = ax * a2.x, iny = ay * a2.y;
        int sw = (rl & 3) << 2;
        int cc = (2 * lane) ^ sw;                 // even; float4-safe
        *(float4*)&li_in[rl * 64 + cc] = make_float4(lix, inx, liy, iny);
    }
    __syncthreads();

    // ---- Phase 3: dual GEMM + bias + leaky relu + row L2 normalize ----
    int jg = tid & 15;
    int rt = tid >> 4;
    int sw = (rt & 3) << 2;

    float4 bb1 = *(const float4*)(b1 + jg * 4);
    float4 bb2 = *(const float4*)(b2 + jg * 4);
    u64 acc01[4], acc23[4];
    {
        u64 i01 = pack2(bb1.x + bb2.x, bb1.y + bb2.y);
        u64 i23 = pack2(bb1.z + bb2.z, bb1.w + bb2.w);
#pragma unroll
        for (int q = 0; q < 4; q++) { acc01[q] = i01; acc23[q] = i23; }
    }

#pragma unroll 4
    for (int k = 0; k < 64; k++) {
        float4 w1 = *(const float4*)&W1s[k * 64 + jg * 4];
        float4 w2 = *(const float4*)&W2s[k * 64 + jg * 4];
        u64 w1a = pack2(w1.x, w1.y), w1b = pack2(w1.z, w1.w);
        u64 w2a = pack2(w2.x, w2.y), w2b = pack2(w2.z, w2.w);
        int kc = k ^ sw;
#pragma unroll
        for (int q = 0; q < 4; q++) {
            float2 fg = li_in[(rt + 16 * q) * 64 + kc];
            u64 ff = pack2(fg.x, fg.x);
            u64 gg = pack2(fg.y, fg.y);
            acc01[q] = fma2(ff, w1a, acc01[q]);
            acc01[q] = fma2(gg, w2a, acc01[q]);
            acc23[q] = fma2(ff, w1b, acc23[q]);
            acc23[q] = fma2(gg, w2b, acc23[q]);
        }
    }

    bool write_h = (layer + 1) < N_LAYERS;
    __half* xo_h = g_Xh + (size_t)(layer + 1) * NE;

#pragma unroll
    for (int q = 0; q < 4; q++) {
        int rg = base + rt + 16 * q;
        float a0, a1, a2, a3;
        unpack2(acc01[q], a0, a1);
        unpack2(acc23[q], a2, a3);
        a0 = a0 > 0.f ? a0 : 0.01f * a0;
        a1 = a1 > 0.f ? a1 : 0.01f * a1;
        a2 = a2 > 0.f ? a2 : 0.01f * a2;
        a3 = a3 > 0.f ? a3 : 0.01f * a3;
        float ss = a0 * a0 + a1 * a1 + a2 * a2 + a3 * a3;
        ss += __shfl_xor_sync(0xffffffffu, ss, 1);
        ss += __shfl_xor_sync(0xffffffffu, ss, 2);
        ss += __shfl_xor_sync(0xffffffffu, ss, 4);
        ss += __shfl_xor_sync(0xffffffffu, ss, 8);
        float inv = 1.0f / fmaxf(sqrtf(ss), 1e-12f);
        if (rg < N_NODES) {
            float o0 = a0 * inv, o1 = a1 * inv, o2 = a2 * inv, o3 = a3 * inv;
            *(float4*)(xo + (size_t)rg * EMB + jg * 4) =
                make_float4(o0, o1, o2, o3);
            if (write_h) {
                __half2 h0 = __floats2half2_rn(o0, o1);
                __half2 h1 = __floats2half2_rn(o2, o3);
                *(uint2*)(xo_h + (size_t)rg * EMB + jg * 4) =
                    make_uint2(*(unsigned*)&h0, *(unsigned*)&h1);
            }
        }
    }
}

// ---------------- BPR loss ----------------------------------------------------
__global__ void loss_kernel(const int* __restrict__ u,
                            const int* __restrict__ ii,
                            const int* __restrict__ jj,
                            float* __restrict__ out) {
    int gw   = (blockIdx.x * blockDim.x + threadIdx.x) >> 5;
    int lane = threadIdx.x & 31;

    float contrib = 0.f;
    if (gw < BATCH) {
        int uu = u[gw];
        int pi = N_USERS + ii[gw];
        int nj = N_USERS + jj[gw];
        float dui = 0.f, duj = 0.f, l2 = 0.f;
#pragma unroll
        for (int c = 0; c < N_LAYERS + 1; c++) {
            const float* base = g_X + (size_t)c * NE;
            float2 uv = *(const float2*)(base + (size_t)uu * EMB + lane * 2);
            float2 pv = *(const float2*)(base + (size_t)pi * EMB + lane * 2);
            float2 nv = *(const float2*)(base + (size_t)nj * EMB + lane * 2);
            dui += uv.x * pv.x + uv.y * pv.y;
            duj += uv.x * nv.x + uv.y * nv.y;
            l2  += uv.x * uv.x + uv.y * uv.y
                 + pv.x * pv.x + pv.y * pv.y
                 + nv.x * nv.x + nv.y * nv.y;
        }
#pragma unroll
        for (int o = 16; o; o >>= 1) {
            dui += __shfl_xor_sync(0xffffffffu, dui, o);
            duj += __shfl_xor_sync(0xffffffffu, duj, o);
            l2  += __shfl_xor_sync(0xffffffffu, l2,  o);
        }
        if (lane == 0) {
            float xv = dui - duj;
            float ls = fminf(xv, 0.f) - log1pf(expf(-fabsf(xv)));
            contrib = (-ls + REG_C * 0.5f * l2) * (1.0f / (float)BATCH);
        }
    }

    __shared__ float sred[8];
    if (lane == 0) sred[threadIdx.x >> 5] = contrib;
    __syncthreads();
    if (threadIdx.x == 0) {
        float s = 0.f;
#pragma unroll
        for (int q = 0; q < 8; q++) s += sred[q];
        atomicAdd(out, s);
    }
}

// ---------------------------------------------------------------------------
extern "C" void kernel_launch(void* const* d_in, const int* in_sizes, int n_in,
                              void* d_out, int out_size) {
    const int*   rows     = (const int*)  d_in[0];
    const int*   cols     = (const int*)  d_in[1];
    const float* vals     = (const float*)d_in[2];
    const float* user_emb = (const float*)d_in[3];
    const float* item_emb = (const float*)d_in[4];
    const float* W_one    = (const float*)d_in[5];
    const float* b_one    = (const float*)d_in[6];
    const float* W_two    = (const float*)d_in[7];
    const float* b_two    = (const float*)d_in[8];
    const int*   u        = (const int*)  d_in[9];
    const int*   i        = (const int*)  d_in[10];
    const int*   j        = (const int*)  d_in[11];
    float* out = (float*)d_out;
    (void)in_sizes; (void)n_in; (void)out_size;

    const int FUSED_SMEM = 65536 + ECAP * 8 + 512;   // W + li_in + edges + rs

    cudaFuncSetAttribute(fused_layer_kernel,
                         cudaFuncAttributeMaxDynamicSharedMemorySize,
                         FUSED_SMEM);

    // CSR build + ego copy
    hist_ego_kernel<<<HIST_GRID + EGO_GRID, 256>>>(rows, user_emb, item_emb, out);
    scan1_kernel<<<HIST_BLOCKS, 256>>>();
    scan23_kernel<<<HIST_BLOCKS, 256>>>();
    scatter_kernel<<<HIST_GRID, 256>>>(rows, cols, vals);

    for (int k = 0; k < N_LAYERS; k++)
        fused_layer_kernel<<<LGRID, 256, FUSED_SMEM>>>(
            W_one + k * EMB * EMB, b_one + k * EMB,
            W_two + k * EMB * EMB, b_two + k * EMB, k);

    loss_kernel<<<BATCH / 8, 256>>>(u, i, j, out);
}

// round 10
// speedup vs baseline: 1.4033x; 1.4033x over previous
#include <cuda_runtime.h>
#include <math.h>

#define N_USERS 100000
#define N_NODES 150000
#define NNZ     4800000
#define EMB     64
#define N_LAYERS 3
#define BATCH   4096
#define REG_C   1e-5f
#define NE      (N_NODES * EMB)
#define HIST_SZ 150016
#define NBLK    586                      // scan blocks: 586*256 = 150016
#define HIST_GRID (NNZ / 256)            // 18750
#define EGO_GRID ((NE / 4) / 256)        // 9375

typedef unsigned long long u64;

// ---------------- scratch (alloc-free rule: __device__ globals) ------------
__device__ float g_X[(N_LAYERS + 1) * NE];   // 153.6 MB fp32 planes
__device__ float g_sideL[NE];                // 38.4 MB
__device__ int   g_hist[HIST_SZ];            // zero at load; self-zeroed each pass
__device__ int   g_row_start[HIST_SZ];
__device__ int   g_cursor[HIST_SZ];
__device__ int   g_blocksum[NBLK];
__device__ uint2 g_edges[NNZ];               // (col, val) sorted by row
__device__ volatile unsigned g_bar_gen;      // grid-barrier generation
__device__ unsigned g_bar_ctr;               // grid-barrier arrival counter

// ---------------- f32x2 packed-math helpers --------------------------------
__device__ __forceinline__ u64 pack2(float lo, float hi) {
    u64 r; asm("mov.b64 %0,{%1,%2};" : "=l"(r) : "f"(lo), "f"(hi)); return r;
}
__device__ __forceinline__ void unpack2(u64 v, float& lo, float& hi) {
    asm("mov.b64 {%0,%1},%2;" : "=f"(lo), "=f"(hi) : "l"(v));
}
__device__ __forceinline__ u64 fma2(u64 a, u64 b, u64 c) {
    u64 d; asm("fma.rn.f32x2 %0,%1,%2,%3;" : "=l"(d) : "l"(a), "l"(b), "l"(c));
    return d;
}

// ---------------- fused: out=0 + edge histogram + ego concat-copy -----------
__global__ void hist_ego_kernel(const int* __restrict__ rows,
                                const float* __restrict__ ue,
                                const float* __restrict__ ie,
                                float* out) {
    int b = blockIdx.x;
    if (b == 0 && threadIdx.x == 0) *out = 0.f;
    if (b < HIST_GRID) {
        int e = b * 256 + threadIdx.x;
        atomicAdd(&g_hist[rows[e]], 1);
    } else {
        int idx = (b - HIST_GRID) * 256 + threadIdx.x;   // float4 index
        const int UF = (N_USERS * EMB) / 4;
        float4 v = (idx < UF) ? ((const float4*)ue)[idx]
                              : ((const float4*)ie)[idx - UF];
        ((float4*)g_X)[idx] = v;
    }
}

// ---------------- single-kernel 3-stage scan (in-kernel grid barrier) -------
// 586 blocks x 256 thr, ~2KB smem, low regs -> all co-resident in wave 1, so
// a generation spin barrier is safe, deterministic, and graph-capturable.
__global__ void __launch_bounds__(256) scan123_kernel() {
    __shared__ int s[256];
    __shared__ int red[256];
    int t = threadIdx.x;
    int b = blockIdx.x;
    int i = b * 256 + t;

    // stage 1: per-block inclusive scan (self-zero hist for next replay)
    int v = g_hist[i];
    g_hist[i] = 0;
    s[t] = v; __syncthreads();
#pragma unroll
    for (int off = 1; off < 256; off <<= 1) {
        int add = (t >= off) ? s[t - off] : 0;
        __syncthreads();
        s[t] += add;
        __syncthreads();
    }
    if (t == 255) g_blocksum[b] = s[255];

    // grid barrier: publish blocksums, then release all blocks
    __threadfence();
    __syncthreads();
    if (t == 0) {
        unsigned gen = g_bar_gen;
        __threadfence();
        unsigned old = atomicAdd(&g_bar_ctr, 1u);
        if (old == NBLK - 1) {
            g_bar_ctr = 0;          // reset BEFORE release (replay-safe)
            __threadfence();
            g_bar_gen = gen + 1;    // release
        } else {
            while (g_bar_gen == gen) { }
        }
    }
    __syncthreads();
    __threadfence();

    // stage 2+3: block prefix from raw blocksums, write row_start + cursor
    int acc = 0;
    for (int k = t; k < b; k += 256) acc += g_blocksum[k];
    red[t] = acc; __syncthreads();
#pragma unroll
    for (int off = 128; off; off >>= 1) {
        if (t < off) red[t] += red[t + off];
        __syncthreads();
    }
    int val = (s[t] - v) + red[0];   // local exclusive + global prefix
    g_row_start[i] = val;
    g_cursor[i]    = val;
}

// ---------------- scatter edges into CSR order (at ATOMG floor) -------------
__global__ void scatter_kernel(const int* __restrict__ rows,
                               const int* __restrict__ cols,
                               const float* __restrict__ vals) {
    int e = blockIdx.x * 256 + threadIdx.x;
    int r = rows[e];
    int pos = atomicAdd(&g_cursor[r], 1);
    g_edges[pos] = make_uint2((unsigned)cols[e], __float_as_uint(vals[e]));
}

// ---------------- SpMM (CSR, exact R2 body): warp per row, MLP=4 ------------
__global__ void spmm_csr_kernel(int layer) {
    int w    = (blockIdx.x * blockDim.x + threadIdx.x) >> 5;
    int lane = threadIdx.x & 31;
    if (w >= N_NODES) return;
    const float* __restrict__ x = g_X + (size_t)layer * NE;
    int s = __ldg(&g_row_start[w]);
    int e = __ldg(&g_row_start[w + 1]);

    float ax = 0.f, ay = 0.f;
    int t = s;
    for (; t + 4 <= e; t += 4) {
        uint2 k0 = g_edges[t + 0];
        uint2 k1 = g_edges[t + 1];
        uint2 k2 = g_edges[t + 2];
        uint2 k3 = g_edges[t + 3];
        float2 x0 = *(const float2*)(x + (size_t)k0.x * EMB + lane * 2);
        float2 x1 = *(const float2*)(x + (size_t)k1.x * EMB + lane * 2);
        float2 x2 = *(const float2*)(x + (size_t)k2.x * EMB + lane * 2);
        float2 x3 = *(const float2*)(x + (size_t)k3.x * EMB + lane * 2);
        float v0 = __uint_as_float(k0.y), v1 = __uint_as_float(k1.y);
        float v2 = __uint_as_float(k2.y), v3 = __uint_as_float(k3.y);
        ax += v0 * x0.x + v1 * x1.x + v2 * x2.x + v3 * x3.x;
        ay += v0 * x0.y + v1 * x1.y + v2 * x2.y + v3 * x3.y;
    }
    for (; t < e; t++) {
        uint2 kv = g_edges[t];
        float2 xv = *(const float2*)(x + (size_t)kv.x * EMB + lane * 2);
        float v = __uint_as_float(kv.y);
        ax += v * xv.x;
        ay += v * xv.y;
    }
    *(float2*)(g_sideL + (size_t)w * EMB + lane * 2) = make_float2(ax, ay);
}

// ---------------- Fused layer (exact R2): GEMMx2+bias+leaky+normalize -------
__global__ void layer_kernel(const float* __restrict__ W1,
                             const float* __restrict__ b1,
                             const float* __restrict__ W2,
                             const float* __restrict__ b2,
                             int layer) {
    extern __shared__ float sm[];
    float*  W1s   = sm;                       // 4096 floats
    float*  W2s   = sm + 4096;                // 4096 floats
    float2* li_in = (float2*)(sm + 8192);     // 64x64 float2 (32KB)

    const float* __restrict__ xk = g_X + (size_t)layer * NE;
    float* __restrict__ xo       = g_X + (size_t)(layer + 1) * NE;

    int tid = threadIdx.x;
#pragma unroll
    for (int it = 0; it < 4; it++) {
        int idx = it * 256 + tid;
        ((float4*)W1s)[idx] = ((const float4*)W1)[idx];
        ((float4*)W2s)[idx] = ((const float4*)W2)[idx];
    }

    int jg = tid & 15;
    int rt = tid >> 4;
    int sw = (rt & 3) << 2;
    int cb = (jg * 4) ^ sw;
    int base_row = blockIdx.x * 64;

#pragma unroll
    for (int q = 0; q < 4; q++) {
        int rl = rt + 16 * q;
        int rg = base_row + rl;
        float4 li4, in4;
        if (rg < N_NODES) {
            float4 s4 = *(const float4*)(g_sideL + (size_t)rg * EMB + jg * 4);
            float4 a4 = *(const float4*)(xk      + (size_t)rg * EMB + jg * 4);
            li4 = make_float4(s4.x + a4.x, s4.y + a4.y, s4.z + a4.z, s4.w + a4.w);
            in4 = make_float4(s4.x * a4.x, s4.y * a4.y, s4.z * a4.z, s4.w * a4.w);
        } else {
            li4 = make_float4(0.f, 0.f, 0.f, 0.f);
            in4 = li4;
        }
        float2* p = &li_in[rl * 64 + cb];
        *(float4*)(p)     = make_float4(li4.x, in4.x, li4.y, in4.y);
        *(float4*)(p + 2) = make_float4(li4.z, in4.z, li4.w, in4.w);
    }
    __syncthreads();

    float4 bb1 = *(const float4*)(b1 + jg * 4);
    float4 bb2 = *(const float4*)(b2 + jg * 4);
    u64 acc01[4], acc23[4];
    {
        u64 i01 = pack2(bb1.x + bb2.x, bb1.y + bb2.y);
        u64 i23 = pack2(bb1.z + bb2.z, bb1.w + bb2.w);
#pragma unroll
        for (int q = 0; q < 4; q++) { acc01[q] = i01; acc23[q] = i23; }
    }

#pragma unroll 4
    for (int k = 0; k < 64; k++) {
        float4 w1 = *(const float4*)&W1s[k * 64 + jg * 4];
        float4 w2 = *(const float4*)&W2s[k * 64 + jg * 4];
        u64 w1a = pack2(w1.x, w1.y), w1b = pack2(w1.z, w1.w);
        u64 w2a = pack2(w2.x, w2.y), w2b = pack2(w2.z, w2.w);
        int kc = k ^ sw;
#pragma unroll
        for (int q = 0; q < 4; q++) {
            float2 fg = li_in[(rt + 16 * q) * 64 + kc];
            u64 ff = pack2(fg.x, fg.x);
            u64 gg = pack2(fg.y, fg.y);
            acc01[q] = fma2(ff, w1a, acc01[q]);
            acc01[q] = fma2(gg, w2a, acc01[q]);
            acc23[q] = fma2(ff, w1b, acc23[q]);
            acc23[q] = fma2(gg, w2b, acc23[q]);
        }
    }

#pragma unroll
    for (int q = 0; q < 4; q++) {
        int rg = base_row + rt + 16 * q;
        float a0, a1, a2, a3;
        unpack2(acc01[q], a0, a1);
        unpack2(acc23[q], a2, a3);
        a0 = a0 > 0.f ? a0 : 0.01f * a0;
        a1 = a1 > 0.f ? a1 : 0.01f * a1;
        a2 = a2 > 0.f ? a2 : 0.01f * a2;
        a3 = a3 > 0.f ? a3 : 0.01f * a3;
        float ss = a0 * a0 + a1 * a1 + a2 * a2 + a3 * a3;
        ss += __shfl_xor_sync(0xffffffffu, ss, 1);
        ss += __shfl_xor_sync(0xffffffffu, ss, 2);
        ss += __shfl_xor_sync(0xffffffffu, ss, 4);
        ss += __shfl_xor_sync(0xffffffffu, ss, 8);
        float inv = 1.0f / fmaxf(sqrtf(ss), 1e-12f);
        if (rg < N_NODES)
            *(float4*)(xo + (size_t)rg * EMB + jg * 4) =
                make_float4(a0 * inv, a1 * inv, a2 * inv, a3 * inv);
    }
}

// ---------------- BPR loss ----------------------------------------------------
__global__ void loss_kernel(const int* __restrict__ u,
                            const int* __restrict__ ii,
                            const int* __restrict__ jj,
                            float* __restrict__ out) {
    int gw   = (blockIdx.x * blockDim.x + threadIdx.x) >> 5;
    int lane = threadIdx.x & 31;

    float contrib = 0.f;
    if (gw < BATCH) {
        int uu = u[gw];
        int pi = N_USERS + ii[gw];
        int nj = N_USERS + jj[gw];
        float dui = 0.f, duj = 0.f, l2 = 0.f;
#pragma unroll
        for (int c = 0; c < N_LAYERS + 1; c++) {
            const float* base = g_X + (size_t)c * NE;
            float2 uv = *(const float2*)(base + (size_t)uu * EMB + lane * 2);
            float2 pv = *(const float2*)(base + (size_t)pi * EMB + lane * 2);
            float2 nv = *(const float2*)(base + (size_t)nj * EMB + lane * 2);
            dui += uv.x * pv.x + uv.y * pv.y;
            duj += uv.x * nv.x + uv.y * nv.y;
            l2  += uv.x * uv.x + uv.y * uv.y
                 + pv.x * pv.x + pv.y * pv.y
                 + nv.x * nv.x + nv.y * nv.y;
        }
#pragma unroll
        for (int o = 16; o; o >>= 1) {
            dui += __shfl_xor_sync(0xffffffffu, dui, o);
            duj += __shfl_xor_sync(0xffffffffu, duj, o);
            l2  += __shfl_xor_sync(0xffffffffu, l2,  o);
        }
        if (lane == 0) {
            float xv = dui - duj;
            float ls = fminf(xv, 0.f) - log1pf(expf(-fabsf(xv)));
            contrib = (-ls + REG_C * 0.5f * l2) * (1.0f / (float)BATCH);
        }
    }

    __shared__ float sred[8];
    if (lane == 0) sred[threadIdx.x >> 5] = contrib;
    __syncthreads();
    if (threadIdx.x == 0) {
        float s = 0.f;
#pragma unroll
        for (int q = 0; q < 8; q++) s += sred[q];
        atomicAdd(out, s);
    }
}

// ---------------------------------------------------------------------------
extern "C" void kernel_launch(void* const* d_in, const int* in_sizes, int n_in,
                              void* d_out, int out_size) {
    const int*   rows     = (const int*)  d_in[0];
    const int*   cols     = (const int*)  d_in[1];
    const float* vals     = (const float*)d_in[2];
    const float* user_emb = (const float*)d_in[3];
    const float* item_emb = (const float*)d_in[4];
    const float* W_one    = (const float*)d_in[5];
    const float* b_one    = (const float*)d_in[6];
    const float* W_two    = (const float*)d_in[7];
    const float* b_two    = (const float*)d_in[8];
    const int*   u        = (const int*)  d_in[9];
    const int*   i        = (const int*)  d_in[10];
    const int*   j        = (const int*)  d_in[11];
    float* out = (float*)d_out;
    (void)in_sizes; (void)n_in; (void)out_size;

    cudaFuncSetAttribute(layer_kernel,
                         cudaFuncAttributeMaxDynamicSharedMemorySize, 65536);

    hist_ego_kernel<<<HIST_GRID + EGO_GRID, 256>>>(rows, user_emb, item_emb, out);
    scan123_kernel<<<NBLK, 256>>>();
    scatter_kernel<<<HIST_GRID, 256>>>(rows, cols, vals);

    for (int k = 0; k < N_LAYERS; k++) {
        spmm_csr_kernel<<<(N_NODES * 32) / 256, 256>>>(k);   // k=0 -> launch #4
        layer_kernel<<<(N_NODES + 63) / 64, 256, 65536>>>(
            W_one + k * EMB * EMB, b_one + k * EMB,
            W_two + k * EMB * EMB, b_two + k * EMB, k);
    }

    loss_kernel<<<BATCH / 8, 256>>>(u, i, j, out);
}